// round 8
// baseline (speedup 1.0000x reference)
#include <cuda_runtime.h>
#include <cuda_bf16.h>
#include <math.h>
#include <stdint.h>

// Problem constants
#define B_  8
#define S_  16
#define C_  32
#define P_  64
#define E_  768
#define M_  512          // S*C
#define L_  32768        // M*P
#define NE_ 1000000
#define TMAXR 100096     // padded table rows = 782*128
#define NCOL 128         // B*S span columns
#define HSZ  2048        // stats hash slots

// GEMM tiling: BK=64, 12 chunks, 144B padded rows
#define KT   12
#define LDAE 72          // bf16 elems per smem row (144B)
#define ROWBY 144
#define CHBY (128*ROWBY) // 18432 bytes per staged chunk
#define CHEL (128*LDAE)  // 9216 elems

// Scratch (device globals)
__device__ __nv_bfloat16  g_scores[(size_t)TMAXR * NCOL];   // 25.6 MB
__device__ __nv_bfloat16  g_Bs[KT * CHEL];                  // pre-laid-out span chunks
__device__ float g_sum1[B_ * M_];
__device__ float g_sscore[B_ * S_];
__device__ int   g_patch_q[B_ * HSZ];
__device__ float g_patch_v[B_ * HSZ];
__device__ float g_max[B_];
__device__ float g_invden[B_];
__device__ float g_bg[B_];

// ---------------------------------------------------------------------------
// helpers
// ---------------------------------------------------------------------------
__device__ __forceinline__ uint32_t smem_u32(const void* p) {
    uint32_t a;
    asm("{ .reg .u64 t; cvta.to.shared.u64 t, %1; cvt.u32.u64 %0, t; }"
        : "=r"(a) : "l"(p));
    return a;
}
__device__ __forceinline__ void cp_async16(uint32_t smem_dst, const void* gmem_src) {
    asm volatile("cp.async.cg.shared.global [%0], [%1], 16;\n" :: "r"(smem_dst), "l"(gmem_src));
}
__device__ __forceinline__ uint32_t packbf2(float lo, float hi) {
    __nv_bfloat162 h = __floats2bfloat162_rn(lo, hi);
    return *reinterpret_cast<uint32_t*>(&h);
}
__device__ __forceinline__ void ldsm4(uint32_t* r, uint32_t addr) {
    asm volatile("ldmatrix.sync.aligned.m8n8.x4.shared.b16 {%0,%1,%2,%3}, [%4];"
                 : "=r"(r[0]), "=r"(r[1]), "=r"(r[2]), "=r"(r[3]) : "r"(addr));
}
__device__ __forceinline__ void mma16816(float* d, const uint32_t* a, const uint32_t* b) {
    asm volatile(
        "mma.sync.aligned.m16n8k16.row.col.f32.bf16.bf16.f32 "
        "{%0,%1,%2,%3}, {%4,%5,%6,%7}, {%8,%9}, {%0,%1,%2,%3};\n"
        : "+f"(d[0]), "+f"(d[1]), "+f"(d[2]), "+f"(d[3])
        : "r"(a[0]), "r"(a[1]), "r"(a[2]), "r"(a[3]), "r"(b[0]), "r"(b[1]));
}

// ---------------------------------------------------------------------------
// Kernel 0a/0b: spans (128x768 f32) -> bf16 chunks in smem tile layout
// chunk kt: rows n=0..127, cols kt*64..+64, row stride LDAE elems.
// ---------------------------------------------------------------------------
__global__ __launch_bounds__(256) void prep_spans(const float* __restrict__ spans, int half)
{
    const int idx = half * (NCOL * E_ / 2) + blockIdx.x * 256 + threadIdx.x;
    const int n = idx / E_, k = idx % E_;
    const int kt = k >> 6, c = k & 63;
    g_Bs[kt * CHEL + n * LDAE + c] = __float2bfloat16(spans[idx]);
}

// ---------------------------------------------------------------------------
// Kernel 0c: span_scores[b,s] = dot(span_embs[b,s], span_W) + span_b
// ---------------------------------------------------------------------------
__global__ __launch_bounds__(512) void sscore_kernel(
    const float* __restrict__ span_embs,
    const float* __restrict__ span_W,
    const float* __restrict__ span_b)
{
    const int b = blockIdx.x;
    const int s = threadIdx.x >> 5, lane = threadIdx.x & 31;
    const float* v = span_embs + ((size_t)b * S_ + s) * E_;
    float d = 0.f;
    #pragma unroll 4
    for (int k = lane; k < E_; k += 32) d += v[k] * span_W[k];
    #pragma unroll
    for (int o = 16; o; o >>= 1) d += __shfl_xor_sync(0xffffffffu, d, o);
    if (lane == 0) g_sscore[b * S_ + s] = d + span_b[0];
}

// ---------------------------------------------------------------------------
// Kernel 1 (4th launch -> profiled): bf16 mma.sync GEMM, BK=64 (12 chunks)
// 2-stage A (reg->STS two phases) + 2-stage cp.async B.  Dynamic smem 72KB.
// ---------------------------------------------------------------------------
__global__ void __launch_bounds__(256, 2) gemm_mma(const float* __restrict__ table, int T)
{
    extern __shared__ __align__(16) char smem[];
    const uint32_t base = smem_u32(smem);
    const uint32_t uA[2] = { base,              base + CHBY };
    const uint32_t uB[2] = { base + 2 * CHBY,   base + 3 * CHBY };

    const int tid  = threadIdx.x;
    const int lane = tid & 31;
    const int warp = tid >> 5;
    const int wm   = warp & 3;
    const int wn   = warp >> 2;

    // A staging: thread -> row = tid>>1, half = tid&1 covering 32 f32 cols (2 phases of 16)
    const int arow = tid >> 1, ahalf = tid & 1;
    const long grow = (long)blockIdx.x * 128 + arow;
    const bool rv = grow < T;
    const float* srcA = table + grow * (long)E_ + ahalf * 32;
    const uint32_t aOff = (uint32_t)(arow * ROWBY + ahalf * 64);

    const uint32_t rowA = (uint32_t)((wm * 32 + (lane & 15)) * ROWBY + ((lane >> 4) & 1) * 16);
    const uint32_t rowB = (uint32_t)((wn * 64 + ((lane >> 4) & 1) * 8 + (lane & 7)) * ROWBY
                                     + ((lane >> 3) & 1) * 16);

    float acc[2][8][4];
    #pragma unroll
    for (int i = 0; i < 2; i++)
        #pragma unroll
        for (int j = 0; j < 8; j++)
            #pragma unroll
            for (int k = 0; k < 4; k++) acc[i][j][k] = 0.f;

    float4 r4[4];

    // load phase p (16 f32) of chunk kt into r4
    #define LDA_P(kt, p) do {                                                   \
        if (rv) {                                                               \
            _Pragma("unroll")                                                   \
            for (int i = 0; i < 4; i++)                                         \
                r4[i] = *(const float4*)(srcA + (kt) * 64 + (p) * 16 + i * 4);  \
        } else {                                                                \
            _Pragma("unroll")                                                   \
            for (int i = 0; i < 4; i++) r4[i] = make_float4(0.f,0.f,0.f,0.f);   \
        }                                                                       \
    } while (0)

    #define STS_P(st, p) do {                                                   \
        _Pragma("unroll")                                                       \
        for (int i = 0; i < 4; i++) {                                           \
            uint32_t p0 = packbf2(r4[i].x, r4[i].y);                            \
            uint32_t p1 = packbf2(r4[i].z, r4[i].w);                            \
            asm volatile("st.shared.v2.b32 [%0], {%1,%2};\n"                    \
                :: "r"(uA[st] + aOff + (p) * 32 + i * 8), "r"(p0), "r"(p1));    \
        }                                                                       \
    } while (0)

    #define CP_B(st, kt) do {                                                   \
        const char* bs = (const char*)g_Bs + (size_t)(kt) * CHBY;               \
        _Pragma("unroll")                                                       \
        for (int r = 0; r < 4; r++)                                             \
            cp_async16(uB[st] + tid * 16 + r * 4096, bs + tid * 16 + r * 4096); \
        if (tid < 128)                                                          \
            cp_async16(uB[st] + 16384 + tid * 16, bs + 16384 + tid * 16);       \
        asm volatile("cp.async.commit_group;\n");                               \
    } while (0)

    #define COMPUTE_K16(ua, ub, k16) do {                                       \
        uint32_t aF[2][4];                                                      \
        ldsm4(aF[0], (ua) + rowA + (k16) * 32);                                 \
        ldsm4(aF[1], (ua) + rowA + 2304 + (k16) * 32);                          \
        uint32_t bF[8][2];                                                      \
        _Pragma("unroll")                                                       \
        for (int tp = 0; tp < 4; tp++) {                                        \
            uint32_t q[4];                                                      \
            ldsm4(q, (ub) + rowB + tp * 2304 + (k16) * 32);                     \
            bF[2*tp][0] = q[0]; bF[2*tp][1] = q[1];                             \
            bF[2*tp+1][0] = q[2]; bF[2*tp+1][1] = q[3];                         \
        }                                                                       \
        _Pragma("unroll")                                                       \
        for (int tm = 0; tm < 2; tm++)                                          \
        _Pragma("unroll")                                                       \
        for (int tn = 0; tn < 8; tn++)                                          \
            mma16816(acc[tm][tn], aF[tm], bF[tn]);                              \
    } while (0)

    // --- prologue: stage chunk 0; preload chunk1 phase0 ---
    LDA_P(0, 0);
    CP_B(0, 0);
    STS_P(0, 0);
    LDA_P(0, 1);
    STS_P(0, 1);
    LDA_P(1, 0);
    asm volatile("cp.async.wait_group 0;\n" ::: "memory");
    __syncthreads();

    for (int kt = 0; kt < KT; kt++) {
        const int cur = kt & 1, nxt = cur ^ 1;
        const uint32_t ua = uA[cur], ub = uB[cur];

        if (kt + 1 < KT) {
            STS_P(nxt, 0);                  // r4 holds (kt+1, p0)
            LDA_P(kt + 1, 1);
            CP_B(nxt, kt + 1);
        }

        COMPUTE_K16(ua, ub, 0);
        COMPUTE_K16(ua, ub, 1);

        if (kt + 1 < KT) {
            STS_P(nxt, 1);                  // r4 holds (kt+1, p1)
            if (kt + 2 < KT) LDA_P(kt + 2, 0);
        }

        COMPUTE_K16(ua, ub, 2);
        COMPUTE_K16(ua, ub, 3);

        if (kt + 1 < KT) {
            asm volatile("cp.async.wait_group 0;\n" ::: "memory");
            __syncthreads();
        }
    }

    // epilogue: bf16 pairs (rows padded to TMAXR: no guard)
    const long row0 = (long)blockIdx.x * 128 + wm * 32 + (lane >> 2);
    const int  col0 = wn * 64 + (lane & 3) * 2;
    #pragma unroll
    for (int tm = 0; tm < 2; tm++) {
        #pragma unroll
        for (int tn = 0; tn < 8; tn++) {
            *(uint32_t*)&g_scores[(size_t)(row0 + tm*16)     * NCOL + col0 + tn*8] =
                packbf2(acc[tm][tn][0], acc[tm][tn][1]);
            *(uint32_t*)&g_scores[(size_t)(row0 + tm*16 + 8) * NCOL + col0 + tn*8] =
                packbf2(acc[tm][tn][2], acc[tm][tn][3]);
        }
    }
    #undef LDA_P
    #undef STS_P
    #undef CP_B
    #undef COMPUTE_K16
}

// ---------------------------------------------------------------------------
// Kernel 2: embedding-bag over precomputed scalar scores (one warp / segment)
// ---------------------------------------------------------------------------
__global__ __launch_bounds__(256) void bag_kernel(
    const int*   __restrict__ ids,
    const int*   __restrict__ offs,
    const float* __restrict__ att)
{
    const int warp = threadIdx.x >> 5;
    const int lane = threadIdx.x & 31;
    const int seg  = blockIdx.x * 8 + warp;
    const int b = seg >> 9;
    const int m = seg & (M_ - 1);
    const int col = b * S_ + (m >> 5);

    const int start = offs[b * M_ + m];
    const int end   = (m == M_ - 1) ? L_ : offs[b * M_ + m + 1];

    float acc = 0.f;
    for (int j = start + lane; j < end; j += 32) {
        const int   id = ids[(size_t)b * L_ + j];
        const float a  = att[(size_t)b * L_ + j];
        acc += a * __bfloat162float(g_scores[(size_t)id * NCOL + col]);
    }
    #pragma unroll
    for (int o = 16; o; o >>= 1) acc += __shfl_xor_sync(0xffffffffu, acc, o);
    if (lane == 0) g_sum1[seg] = acc;
}

// ---------------------------------------------------------------------------
// Kernel 3: finalize = softmax(S) + softmax(M) + hash dedupe + analytic stats
// ---------------------------------------------------------------------------
__global__ __launch_bounds__(512) void finalize_kernel(const int* __restrict__ qids)
{
    const int b = blockIdx.x;
    const int tid = threadIdx.x;
    const int w = tid >> 5, lane = tid & 31;
    const int s = tid >> 5, c = tid & 31;

    __shared__ float s1[M_];
    __shared__ float colmax[C_], colrs[C_];
    __shared__ float redf[16];
    __shared__ int   redi[16];
    __shared__ int   hk[HSZ];
    __shared__ float hv[HSZ];

    s1[tid] = g_sum1[b * M_ + tid];
    #pragma unroll
    for (int i = tid; i < HSZ; i += 512) { hk[i] = -1; hv[i] = 0.f; }
    const float sscore = g_sscore[b * S_ + s];
    const int   q      = qids[b * M_ + tid];
    __syncthreads();

    if (tid < C_) {
        float mx = -1e30f;
        #pragma unroll
        for (int ss = 0; ss < S_; ss++) mx = fmaxf(mx, s1[ss * C_ + tid]);
        float sm = 0.f;
        #pragma unroll
        for (int ss = 0; ss < S_; ss++) sm += __expf(s1[ss * C_ + tid] - mx);
        colmax[tid] = mx;
        colrs[tid] = 1.f / sm;
    }
    __syncthreads();

    const float sm1 = __expf(s1[tid] - colmax[c]) * colrs[c];
    const float m2  = sscore * sm1;

    float mx = m2;
    #pragma unroll
    for (int o = 16; o; o >>= 1) mx = fmaxf(mx, __shfl_xor_sync(0xffffffffu, mx, o));
    if (lane == 0) redf[w] = mx;
    __syncthreads();
    if (tid == 0) {
        float t = redf[0];
        #pragma unroll
        for (int i = 1; i < 16; i++) t = fmaxf(t, redf[i]);
        redf[0] = t;
    }
    __syncthreads();
    const float gmx = redf[0];
    __syncthreads();

    const float e = __expf(m2 - gmx);
    float ssum = e;
    #pragma unroll
    for (int o = 16; o; o >>= 1) ssum += __shfl_xor_sync(0xffffffffu, ssum, o);
    if (lane == 0) redf[w] = ssum;
    __syncthreads();
    if (tid == 0) {
        float t = 0.f;
        #pragma unroll
        for (int i = 0; i < 16; i++) t += redf[i];
        redf[0] = 1.f / t;
    }
    __syncthreads();
    const float cand = e * redf[0];
    __syncthreads();

    if (q < NE_) {
        uint32_t h = (((uint32_t)q * 2654435761u) >> 20) & (HSZ - 1);
        while (true) {
            const int old = atomicCAS(&hk[h], -1, q);
            if (old == -1 || old == q) { atomicAdd(&hv[h], cand); break; }
            h = (h + 1) & (HSZ - 1);
        }
    }
    __syncthreads();

    float hmx = 0.f;
    for (int i = tid; i < HSZ; i += 512)
        if (hk[i] >= 0) hmx = fmaxf(hmx, hv[i]);
    #pragma unroll
    for (int o = 16; o; o >>= 1) hmx = fmaxf(hmx, __shfl_xor_sync(0xffffffffu, hmx, o));
    if (lane == 0) redf[w] = hmx;
    __syncthreads();
    if (tid == 0) {
        float t = 0.f;
        #pragma unroll
        for (int i = 0; i < 16; i++) t = fmaxf(t, redf[i]);
        redf[0] = t;
    }
    __syncthreads();
    const float maxv = redf[0];
    __syncthreads();

    float se = 0.f; int cnt = 0;
    for (int i = tid; i < HSZ; i += 512)
        if (hk[i] >= 0) { se += expf(hv[i] - maxv); cnt++; }
    #pragma unroll
    for (int o = 16; o; o >>= 1) {
        se  += __shfl_xor_sync(0xffffffffu, se, o);
        cnt += __shfl_xor_sync(0xffffffffu, cnt, o);
    }
    if (lane == 0) { redf[w] = se; redi[w] = cnt; }
    __syncthreads();
    if (tid == 0) {
        float ss = 0.f; int cc = 0;
        #pragma unroll
        for (int i = 0; i < 16; i++) { ss += redf[i]; cc += redi[i]; }
        const float denom = (float)(NE_ - cc) * expf(-maxv) + ss;
        const float inv = 1.f / denom;
        g_max[b] = maxv;
        g_invden[b] = inv;
        g_bg[b] = expf(-maxv) * inv;
    }
    for (int i = tid; i < HSZ; i += 512) {
        g_patch_q[b * HSZ + i] = hk[i];
        g_patch_v[b * HSZ + i] = hv[i];
    }
}

// ---------------------------------------------------------------------------
// Kernel 4: fill output with per-batch background (streaming stores)
// ---------------------------------------------------------------------------
__global__ __launch_bounds__(256) void fill_kernel(float4* __restrict__ out)
{
    const int b = blockIdx.y;
    const float bg = g_bg[b];
    float4* o = out + (size_t)b * (NE_ / 4);
    const int stride = gridDim.x * blockDim.x;
    const float4 vv = make_float4(bg, bg, bg, bg);
    for (int i = blockIdx.x * blockDim.x + threadIdx.x; i < NE_ / 4; i += stride)
        __stcs(&o[i], vv);
}

// ---------------------------------------------------------------------------
// Kernel 5: patch candidate positions
// ---------------------------------------------------------------------------
__global__ __launch_bounds__(256) void patch_kernel(float* __restrict__ out)
{
    const int k = blockIdx.x * blockDim.x + threadIdx.x;
    if (k >= B_ * HSZ) return;
    const int b = k >> 11;
    const int qi = g_patch_q[k];
    if (qi >= 0)
        out[(size_t)b * NE_ + qi] = expf(g_patch_v[k] - g_max[b]) * g_invden[b];
}

// ---------------------------------------------------------------------------
extern "C" void kernel_launch(void* const* d_in, const int* in_sizes, int n_in,
                              void* d_out, int out_size)
{
    const float* span_embs = (const float*)d_in[0];
    const int*   ids       = (const int*)d_in[1];
    const int*   offs      = (const int*)d_in[2];
    const float* att       = (const float*)d_in[3];
    const int*   qids      = (const int*)d_in[4];
    const float* table     = (const float*)d_in[5];
    const float* span_W    = (const float*)d_in[6];
    const float* span_b    = (const float*)d_in[7];
    float* out = (float*)d_out;

    const int T = in_sizes[5] / E_;          // 100000
    const int smemBytes = 4 * CHBY;          // 73728

    cudaFuncSetAttribute(gemm_mma, cudaFuncAttributeMaxDynamicSharedMemorySize, smemBytes);

    prep_spans<<<NCOL * E_ / 2 / 256, 256>>>(span_embs, 0);       // 1
    prep_spans<<<NCOL * E_ / 2 / 256, 256>>>(span_embs, 1);       // 2
    sscore_kernel<<<B_, 512>>>(span_embs, span_W, span_b);        // 3
    gemm_mma<<<(T + 127) / 128, 256, smemBytes>>>(table, T);      // 4  <- profiled
    bag_kernel<<<B_ * M_ / 8, 256>>>(ids, offs, att);             // 5
    finalize_kernel<<<B_, 512>>>(qids);                           // 6
    fill_kernel<<<dim3(192, B_), 256>>>((float4*)out);            // 7
    patch_kernel<<<(B_ * HSZ + 255) / 256, 256>>>(out);           // 8
}

// round 9
// speedup vs baseline: 1.2097x; 1.2097x over previous
#include <cuda_runtime.h>
#include <cuda_bf16.h>
#include <math.h>
#include <stdint.h>

// Problem constants
#define B_  8
#define S_  16
#define C_  32
#define P_  64
#define E_  768
#define M_  512          // S*C
#define L_  32768        // M*P
#define NE_ 1000000
#define HSZ 2048         // stats hash slots
#define EV_ 192          // E/4 float4s

// Scratch (device globals)
__device__ float g_sum1[B_ * M_];
__device__ float g_sscore[B_ * S_];
__device__ int   g_patch_q[B_ * HSZ];
__device__ float g_patch_v[B_ * HSZ];
__device__ float g_max[B_];
__device__ float g_invden[B_];
__device__ float g_bg[B_];

// ---------------------------------------------------------------------------
// Kernel A: span_scores[b,s] = dot(span_embs[b,s], span_W) + span_b
// ---------------------------------------------------------------------------
__global__ __launch_bounds__(512) void sscore_kernel(
    const float* __restrict__ span_embs,
    const float* __restrict__ span_W,
    const float* __restrict__ span_b)
{
    const int b = blockIdx.x;
    const int s = threadIdx.x >> 5, lane = threadIdx.x & 31;
    const float* v = span_embs + ((size_t)b * S_ + s) * E_;
    float d = 0.f;
    #pragma unroll 4
    for (int k = lane; k < E_; k += 32) d += v[k] * span_W[k];
    #pragma unroll
    for (int o = 16; o; o >>= 1) d += __shfl_xor_sync(0xffffffffu, d, o);
    if (lane == 0) g_sscore[b * S_ + s] = d + span_b[0];
}

// ---------------------------------------------------------------------------
// Kernel B: fused embedding-bag + dot with span vector (R1-proven, +ILP2).
// One 256-thread block per segment; 8 warps each own 8 of the 64 rows.
// sum1[b,m] = sum_j att_j * dot(table[id_j], span[b, m % 16])
// ---------------------------------------------------------------------------
__global__ __launch_bounds__(256) void bag_dot_kernel(
    const float* __restrict__ span_embs,   // (B,S,E)
    const int*   __restrict__ ids,         // (B,L)
    const int*   __restrict__ offs,        // (B,M)
    const float* __restrict__ att,         // (B,L)
    const float* __restrict__ table,       // (T,E)
    int seg0)
{
    const int seg = blockIdx.x + seg0;     // 0 .. B*M-1
    const int b = seg >> 9;
    const int m = seg & (M_ - 1);

    __shared__ float4 sv[EV_];
    const int tid = threadIdx.x;
    // reference: exp_emb[b, m] = span_embs[b, m % S]  (tile along axis 1)
    const float4* sp = reinterpret_cast<const float4*>(
        span_embs + ((size_t)b * S_ + (m & (S_ - 1))) * E_);
    if (tid < EV_) sv[tid] = sp[tid];
    __syncthreads();

    const int start = offs[b * M_ + m];
    const int end   = (m == M_ - 1) ? L_ : offs[b * M_ + m + 1];

    const int lane = tid & 31;
    const int w    = tid >> 5;             // 8 warps
    const size_t base = (size_t)b * L_;

    float acc = 0.f;
    int j = start + w;
    // paired iterations: rows j and j+8 in flight together (12 indep LDG.128)
    for (; j + 8 < end; j += 16) {
        const int   id0 = ids[base + j];
        const int   id1 = ids[base + j + 8];
        const float a0  = att[base + j];
        const float a1  = att[base + j + 8];
        const float4* r0 = reinterpret_cast<const float4*>(table + (size_t)id0 * E_);
        const float4* r1 = reinterpret_cast<const float4*>(table + (size_t)id1 * E_);
        float d0 = 0.f, d1 = 0.f;
        #pragma unroll
        for (int k = 0; k < 6; k++) {
            const float4 s  = sv[lane + 32 * k];
            const float4 x0 = r0[lane + 32 * k];
            const float4 x1 = r1[lane + 32 * k];
            d0 += x0.x * s.x + x0.y * s.y + x0.z * s.z + x0.w * s.w;
            d1 += x1.x * s.x + x1.y * s.y + x1.z * s.z + x1.w * s.w;
        }
        acc += a0 * d0 + a1 * d1;
    }
    for (; j < end; j += 8) {
        const int   id = ids[base + j];
        const float a  = att[base + j];
        const float4* row = reinterpret_cast<const float4*>(table + (size_t)id * E_);
        float d = 0.f;
        #pragma unroll
        for (int k = 0; k < 6; k++) {
            const float4 s = sv[lane + 32 * k];
            const float4 x = row[lane + 32 * k];
            d += x.x * s.x + x.y * s.y + x.z * s.z + x.w * s.w;
        }
        acc += a * d;
    }

    #pragma unroll
    for (int o = 16; o; o >>= 1) acc += __shfl_xor_sync(0xffffffffu, acc, o);

    __shared__ float wsum[8];
    if (lane == 0) wsum[w] = acc;
    __syncthreads();
    if (tid == 0) {
        float t = 0.f;
        #pragma unroll
        for (int i = 0; i < 8; i++) t += wsum[i];
        g_sum1[seg] = t;
    }
}

// ---------------------------------------------------------------------------
// Kernel C: finalize = softmax(S) + softmax(M) + hash dedupe + analytic stats
// One block (512 threads) per batch.
// ---------------------------------------------------------------------------
__global__ __launch_bounds__(512) void finalize_kernel(const int* __restrict__ qids)
{
    const int b = blockIdx.x;
    const int tid = threadIdx.x;
    const int w = tid >> 5, lane = tid & 31;
    const int s = tid >> 5, c = tid & 31;

    __shared__ float s1[M_];
    __shared__ float colmax[C_], colrs[C_];
    __shared__ float redf[16];
    __shared__ int   redi[16];
    __shared__ int   hk[HSZ];
    __shared__ float hv[HSZ];

    s1[tid] = g_sum1[b * M_ + tid];
    #pragma unroll
    for (int i = tid; i < HSZ; i += 512) { hk[i] = -1; hv[i] = 0.f; }
    const float sscore = g_sscore[b * S_ + s];
    const int   q      = qids[b * M_ + tid];
    __syncthreads();

    // softmax over s (16 values) per column c
    if (tid < C_) {
        float mx = -1e30f;
        #pragma unroll
        for (int ss = 0; ss < S_; ss++) mx = fmaxf(mx, s1[ss * C_ + tid]);
        float sm = 0.f;
        #pragma unroll
        for (int ss = 0; ss < S_; ss++) sm += __expf(s1[ss * C_ + tid] - mx);
        colmax[tid] = mx;
        colrs[tid] = 1.f / sm;
    }
    __syncthreads();

    const float sm1 = __expf(s1[tid] - colmax[c]) * colrs[c];
    const float m2  = sscore * sm1;

    // block softmax over 512 values
    float mx = m2;
    #pragma unroll
    for (int o = 16; o; o >>= 1) mx = fmaxf(mx, __shfl_xor_sync(0xffffffffu, mx, o));
    if (lane == 0) redf[w] = mx;
    __syncthreads();
    if (tid == 0) {
        float t = redf[0];
        #pragma unroll
        for (int i = 1; i < 16; i++) t = fmaxf(t, redf[i]);
        redf[0] = t;
    }
    __syncthreads();
    const float gmx = redf[0];
    __syncthreads();

    const float e = __expf(m2 - gmx);
    float ssum = e;
    #pragma unroll
    for (int o = 16; o; o >>= 1) ssum += __shfl_xor_sync(0xffffffffu, ssum, o);
    if (lane == 0) redf[w] = ssum;
    __syncthreads();
    if (tid == 0) {
        float t = 0.f;
        #pragma unroll
        for (int i = 0; i < 16; i++) t += redf[i];
        redf[0] = 1.f / t;
    }
    __syncthreads();
    const float cand = e * redf[0];
    __syncthreads();

    // hash dedupe (scatter-add collisions); qid == NE dropped
    if (q < NE_) {
        uint32_t h = (((uint32_t)q * 2654435761u) >> 20) & (HSZ - 1);
        while (true) {
            const int old = atomicCAS(&hk[h], -1, q);
            if (old == -1 || old == q) { atomicAdd(&hv[h], cand); break; }
            h = (h + 1) & (HSZ - 1);
        }
    }
    __syncthreads();

    // max over deduped values (0 baseline always present: NE >> nnz)
    float hmx = 0.f;
    for (int i = tid; i < HSZ; i += 512)
        if (hk[i] >= 0) hmx = fmaxf(hmx, hv[i]);
    #pragma unroll
    for (int o = 16; o; o >>= 1) hmx = fmaxf(hmx, __shfl_xor_sync(0xffffffffu, hmx, o));
    if (lane == 0) redf[w] = hmx;
    __syncthreads();
    if (tid == 0) {
        float t = 0.f;
        #pragma unroll
        for (int i = 0; i < 16; i++) t = fmaxf(t, redf[i]);
        redf[0] = t;
    }
    __syncthreads();
    const float maxv = redf[0];
    __syncthreads();

    float se = 0.f; int cnt = 0;
    for (int i = tid; i < HSZ; i += 512)
        if (hk[i] >= 0) { se += expf(hv[i] - maxv); cnt++; }
    #pragma unroll
    for (int o = 16; o; o >>= 1) {
        se  += __shfl_xor_sync(0xffffffffu, se, o);
        cnt += __shfl_xor_sync(0xffffffffu, cnt, o);
    }
    if (lane == 0) { redf[w] = se; redi[w] = cnt; }
    __syncthreads();
    if (tid == 0) {
        float ss = 0.f; int cc = 0;
        #pragma unroll
        for (int i = 0; i < 16; i++) { ss += redf[i]; cc += redi[i]; }
        const float denom = (float)(NE_ - cc) * expf(-maxv) + ss;
        const float inv = 1.f / denom;
        g_max[b] = maxv;
        g_invden[b] = inv;
        g_bg[b] = expf(-maxv) * inv;
    }
    for (int i = tid; i < HSZ; i += 512) {
        g_patch_q[b * HSZ + i] = hk[i];
        g_patch_v[b * HSZ + i] = hv[i];
    }
}

// ---------------------------------------------------------------------------
// Kernel D: fill output with per-batch background (streaming stores)
// ---------------------------------------------------------------------------
__global__ __launch_bounds__(256) void fill_kernel(float4* __restrict__ out)
{
    const int b = blockIdx.y;
    const float bg = g_bg[b];
    float4* o = out + (size_t)b * (NE_ / 4);
    const int stride = gridDim.x * blockDim.x;
    const float4 vv = make_float4(bg, bg, bg, bg);
    for (int i = blockIdx.x * blockDim.x + threadIdx.x; i < NE_ / 4; i += stride)
        __stcs(&o[i], vv);
}

// ---------------------------------------------------------------------------
// Kernel E: patch candidate positions
// ---------------------------------------------------------------------------
__global__ __launch_bounds__(256) void patch_kernel(float* __restrict__ out)
{
    const int k = blockIdx.x * blockDim.x + threadIdx.x;
    if (k >= B_ * HSZ) return;
    const int b = k >> 11;
    const int qi = g_patch_q[k];
    if (qi >= 0)
        out[(size_t)b * NE_ + qi] = expf(g_patch_v[k] - g_max[b]) * g_invden[b];
}

// ---------------------------------------------------------------------------
extern "C" void kernel_launch(void* const* d_in, const int* in_sizes, int n_in,
                              void* d_out, int out_size)
{
    const float* span_embs = (const float*)d_in[0];
    const int*   ids       = (const int*)d_in[1];
    const int*   offs      = (const int*)d_in[2];
    const float* att       = (const float*)d_in[3];
    const int*   qids      = (const int*)d_in[4];
    const float* table     = (const float*)d_in[5];
    const float* span_W    = (const float*)d_in[6];
    const float* span_b    = (const float*)d_in[7];
    float* out = (float*)d_out;

    sscore_kernel<<<B_, 512>>>(span_embs, span_W, span_b);                 // 1
    bag_dot_kernel<<<512, 256>>>(span_embs, ids, offs, att, table, 0);     // 2
    bag_dot_kernel<<<512, 256>>>(span_embs, ids, offs, att, table, 512);   // 3
    bag_dot_kernel<<<3072, 256>>>(span_embs, ids, offs, att, table, 1024); // 4 <- profiled
    finalize_kernel<<<B_, 512>>>(qids);                                    // 5
    fill_kernel<<<dim3(192, B_), 256>>>((float4*)out);                     // 6
    patch_kernel<<<(B_ * HSZ + 255) / 256, 256>>>(out);                    // 7
}

// round 10
// speedup vs baseline: 1.3600x; 1.1242x over previous
#include <cuda_runtime.h>
#include <cuda_bf16.h>
#include <math.h>
#include <stdint.h>

// Problem constants
#define B_  8
#define S_  16
#define C_  32
#define P_  64
#define E_  768
#define M_  512          // S*C
#define L_  32768        // M*P
#define NE_ 1000000
#define HSZ 2048         // stats hash slots
#define EV_ 192          // E/4 float4s

// Scratch (device globals)
__device__ float g_sum1[B_ * M_];
__device__ int   g_patch_q[B_ * HSZ];
__device__ float g_patch_v[B_ * HSZ];
__device__ float g_max[B_];
__device__ float g_invden[B_];
__device__ float g_bg[B_];

// ---------------------------------------------------------------------------
// Kernel 1: fused embedding-bag + dot with span vector (single launch).
// One 256-thread block per segment; 8 warps each own 8 of the 64 rows.
// sum1[b,m] = sum_j att_j * dot(table[id_j], span_embs[b, m % 16])
// ---------------------------------------------------------------------------
__global__ __launch_bounds__(256, 4) void bag_dot_kernel(
    const float* __restrict__ span_embs,   // (B,S,E)
    const int*   __restrict__ ids,         // (B,L)
    const int*   __restrict__ offs,        // (B,M)
    const float* __restrict__ att,         // (B,L)
    const float* __restrict__ table)       // (T,E)
{
    const int seg = blockIdx.x;            // 0 .. B*M-1
    const int b = seg >> 9;
    const int m = seg & (M_ - 1);

    __shared__ float4 sv[EV_];
    const int tid = threadIdx.x;
    const float4* sp = reinterpret_cast<const float4*>(
        span_embs + ((size_t)b * S_ + (m & (S_ - 1))) * E_);
    if (tid < EV_) sv[tid] = sp[tid];
    __syncthreads();

    const int start = offs[b * M_ + m];
    const int end   = (m == M_ - 1) ? L_ : offs[b * M_ + m + 1];

    const int lane = tid & 31;
    const int w    = tid >> 5;             // 8 warps
    const size_t base = (size_t)b * L_;

    float acc = 0.f;
    for (int j = start + w; j < end; j += 8) {
        const int   id = ids[base + j];
        const float a  = att[base + j];
        const float4* row = reinterpret_cast<const float4*>(table + (size_t)id * E_);
        float d = 0.f;
        #pragma unroll
        for (int k = 0; k < 6; k++) {
            const float4 s = sv[lane + 32 * k];
            const float4 x = row[lane + 32 * k];
            d += x.x * s.x + x.y * s.y + x.z * s.z + x.w * s.w;
        }
        acc += a * d;
    }

    #pragma unroll
    for (int o = 16; o; o >>= 1) acc += __shfl_xor_sync(0xffffffffu, acc, o);

    __shared__ float wsum[8];
    if (lane == 0) wsum[w] = acc;
    __syncthreads();
    if (tid == 0) {
        float t = 0.f;
        #pragma unroll
        for (int i = 0; i < 8; i++) t += wsum[i];
        g_sum1[seg] = t;
    }
}

// ---------------------------------------------------------------------------
// Kernel 2: finalize = span-score dot + softmax(S) + softmax(M)
//           + hash dedupe + analytic background stats.  One block per batch.
// ---------------------------------------------------------------------------
__global__ __launch_bounds__(512) void finalize_kernel(
    const int*   __restrict__ qids,
    const float* __restrict__ span_embs,
    const float* __restrict__ span_W,
    const float* __restrict__ span_b)
{
    const int b = blockIdx.x;
    const int tid = threadIdx.x;
    const int w = tid >> 5, lane = tid & 31;
    const int s = tid >> 5, c = tid & 31;

    __shared__ float s1[M_];
    __shared__ float sscoreSm[S_];
    __shared__ float colmax[C_], colrs[C_];
    __shared__ float redf[16];
    __shared__ int   redi[16];
    __shared__ int   hk[HSZ];
    __shared__ float hv[HSZ];

    s1[tid] = g_sum1[b * M_ + tid];
    #pragma unroll
    for (int i = tid; i < HSZ; i += 512) { hk[i] = -1; hv[i] = 0.f; }
    const int q = qids[b * M_ + tid];

    // warp w computes span_scores[b, w]
    {
        const float* v = span_embs + ((size_t)b * S_ + w) * E_;
        float d = 0.f;
        #pragma unroll 4
        for (int k = lane; k < E_; k += 32) d += v[k] * span_W[k];
        #pragma unroll
        for (int o = 16; o; o >>= 1) d += __shfl_xor_sync(0xffffffffu, d, o);
        if (lane == 0) sscoreSm[w] = d + span_b[0];
    }
    __syncthreads();

    // softmax over s (16 values) per column c
    if (tid < C_) {
        float mx = -1e30f;
        #pragma unroll
        for (int ss = 0; ss < S_; ss++) mx = fmaxf(mx, s1[ss * C_ + tid]);
        float sm = 0.f;
        #pragma unroll
        for (int ss = 0; ss < S_; ss++) sm += __expf(s1[ss * C_ + tid] - mx);
        colmax[tid] = mx;
        colrs[tid] = 1.f / sm;
    }
    __syncthreads();

    const float sm1 = __expf(s1[tid] - colmax[c]) * colrs[c];
    const float m2  = sscoreSm[s] * sm1;

    // block softmax over 512 values
    float mx = m2;
    #pragma unroll
    for (int o = 16; o; o >>= 1) mx = fmaxf(mx, __shfl_xor_sync(0xffffffffu, mx, o));
    if (lane == 0) redf[w] = mx;
    __syncthreads();
    if (tid == 0) {
        float t = redf[0];
        #pragma unroll
        for (int i = 1; i < 16; i++) t = fmaxf(t, redf[i]);
        redf[0] = t;
    }
    __syncthreads();
    const float gmx = redf[0];
    __syncthreads();

    const float e = __expf(m2 - gmx);
    float ssum = e;
    #pragma unroll
    for (int o = 16; o; o >>= 1) ssum += __shfl_xor_sync(0xffffffffu, ssum, o);
    if (lane == 0) redf[w] = ssum;
    __syncthreads();
    if (tid == 0) {
        float t = 0.f;
        #pragma unroll
        for (int i = 0; i < 16; i++) t += redf[i];
        redf[0] = 1.f / t;
    }
    __syncthreads();
    const float cand = e * redf[0];
    __syncthreads();

    // hash dedupe (scatter-add collisions); qid == NE dropped
    if (q < NE_) {
        uint32_t h = (((uint32_t)q * 2654435761u) >> 20) & (HSZ - 1);
        while (true) {
            const int old = atomicCAS(&hk[h], -1, q);
            if (old == -1 || old == q) { atomicAdd(&hv[h], cand); break; }
            h = (h + 1) & (HSZ - 1);
        }
    }
    __syncthreads();

    // max over deduped values (0 baseline always present: NE >> nnz)
    float hmx = 0.f;
    for (int i = tid; i < HSZ; i += 512)
        if (hk[i] >= 0) hmx = fmaxf(hmx, hv[i]);
    #pragma unroll
    for (int o = 16; o; o >>= 1) hmx = fmaxf(hmx, __shfl_xor_sync(0xffffffffu, hmx, o));
    if (lane == 0) redf[w] = hmx;
    __syncthreads();
    if (tid == 0) {
        float t = 0.f;
        #pragma unroll
        for (int i = 0; i < 16; i++) t = fmaxf(t, redf[i]);
        redf[0] = t;
    }
    __syncthreads();
    const float maxv = redf[0];
    __syncthreads();

    float se = 0.f; int cnt = 0;
    for (int i = tid; i < HSZ; i += 512)
        if (hk[i] >= 0) { se += expf(hv[i] - maxv); cnt++; }
    #pragma unroll
    for (int o = 16; o; o >>= 1) {
        se  += __shfl_xor_sync(0xffffffffu, se, o);
        cnt += __shfl_xor_sync(0xffffffffu, cnt, o);
    }
    if (lane == 0) { redf[w] = se; redi[w] = cnt; }
    __syncthreads();
    if (tid == 0) {
        float ss = 0.f; int cc = 0;
        #pragma unroll
        for (int i = 0; i < 16; i++) { ss += redf[i]; cc += redi[i]; }
        const float denom = (float)(NE_ - cc) * expf(-maxv) + ss;
        const float inv = 1.f / denom;
        g_max[b] = maxv;
        g_invden[b] = inv;
        g_bg[b] = expf(-maxv) * inv;
    }
    for (int i = tid; i < HSZ; i += 512) {
        g_patch_q[b * HSZ + i] = hk[i];
        g_patch_v[b * HSZ + i] = hv[i];
    }
}

// ---------------------------------------------------------------------------
// Kernel 3: fill output with per-batch background (streaming stores)
// ---------------------------------------------------------------------------
__global__ __launch_bounds__(256) void fill_kernel(float4* __restrict__ out)
{
    const int b = blockIdx.y;
    const float bg = g_bg[b];
    float4* o = out + (size_t)b * (NE_ / 4);
    const int stride = gridDim.x * blockDim.x;
    const float4 vv = make_float4(bg, bg, bg, bg);
    for (int i = blockIdx.x * blockDim.x + threadIdx.x; i < NE_ / 4; i += stride)
        __stcs(&o[i], vv);
}

// ---------------------------------------------------------------------------
// Kernel 4: patch candidate positions
// ---------------------------------------------------------------------------
__global__ __launch_bounds__(256) void patch_kernel(float* __restrict__ out)
{
    const int k = blockIdx.x * blockDim.x + threadIdx.x;
    if (k >= B_ * HSZ) return;
    const int b = k >> 11;
    const int qi = g_patch_q[k];
    if (qi >= 0)
        out[(size_t)b * NE_ + qi] = expf(g_patch_v[k] - g_max[b]) * g_invden[b];
}

// ---------------------------------------------------------------------------
extern "C" void kernel_launch(void* const* d_in, const int* in_sizes, int n_in,
                              void* d_out, int out_size)
{
    const float* span_embs = (const float*)d_in[0];
    const int*   ids       = (const int*)d_in[1];
    const int*   offs      = (const int*)d_in[2];
    const float* att       = (const float*)d_in[3];
    const int*   qids      = (const int*)d_in[4];
    const float* table     = (const float*)d_in[5];
    const float* span_W    = (const float*)d_in[6];
    const float* span_b    = (const float*)d_in[7];
    float* out = (float*)d_out;

    bag_dot_kernel<<<B_ * M_, 256>>>(span_embs, ids, offs, att, table);    // 1
    finalize_kernel<<<B_, 512>>>(qids, span_embs, span_W, span_b);         // 2
    fill_kernel<<<dim3(192, B_), 256>>>((float4*)out);                     // 3
    patch_kernel<<<(B_ * HSZ + 255) / 256, 256>>>(out);                    // 4
}